// round 5
// baseline (speedup 1.0000x reference)
#include <cuda_runtime.h>
#include <cstdint>

#define NN      50000
#define EE      800000
#define ET      (EE + NN)
#define IN_DIM  256
#define HID     32
#define HEADS   4
#define OUT_DIM 40
#define F1      128
#define F2      160
#define SLOPE   0.2f
#define FULLMASK 0xffffffffu

// ---------------- scratch ----------------
__device__ float g_xc1[(size_t)NN * 256];   // [xl1 | xr1]
__device__ float g_xc2[(size_t)NN * 320];   // [xl2 | xr2]
__device__ float g_h  [(size_t)NN * F1];
__device__ int   g_deg[NN];
__device__ int   g_rowptr[NN + 1];
__device__ int   g_cursor[NN];
__device__ int   g_csrsrc[ET];

// ---------------- CSR build ----------------
__global__ void count_kernel(const int* __restrict__ edst)
{
    int idx = blockIdx.x * blockDim.x + threadIdx.x;
    if (idx >= ET) return;
    int d = (idx < EE) ? edst[idx] : idx - EE;
    atomicAdd(&g_deg[d], 1);
}

__global__ void scan_kernel()
{
    __shared__ int ssum[1024];
    int t = threadIdx.x;
    const int CH = (NN + 1023) / 1024;
    int lo = t * CH;
    int hi = min(lo + CH, NN);
    int s = 0;
    for (int i = lo; i < hi; i++) s += g_deg[i];
    ssum[t] = s;
    __syncthreads();
    for (int off = 1; off < 1024; off <<= 1) {
        int v = (t >= off) ? ssum[t - off] : 0;
        __syncthreads();
        ssum[t] += v;
        __syncthreads();
    }
    int base = (t == 0) ? 0 : ssum[t - 1];
    for (int i = lo; i < hi; i++) {
        g_rowptr[i] = base;
        g_cursor[i] = base;
        base += g_deg[i];
    }
    if (t == 0) g_rowptr[NN] = ET;
}

__global__ void scatter_kernel(const int* __restrict__ esrc, const int* __restrict__ edst)
{
    int idx = blockIdx.x * blockDim.x + threadIdx.x;
    if (idx >= ET) return;
    int s, d;
    if (idx < EE) { s = esrc[idx]; d = edst[idx]; }
    else          { s = d = idx - EE; }
    int pos = atomicAdd(&g_cursor[d], 1);
    g_csrsrc[pos] = s;
}

// ---------------- TF32 GEMM, reg-staged double buffer, fused concat+bias ----------------
__device__ __forceinline__ uint32_t f2tf(float f) {
    uint32_t r;
    asm("cvt.rna.tf32.f32 %0, %1;" : "=r"(r) : "f"(f));
    return r;
}

// C[M, 2*Nh] = A[M,K] @ [Wl | Wr] + [bl | br]
__global__ __launch_bounds__(256, 2) void gemm_tf32_fused(
    const float* __restrict__ A, const float* __restrict__ Wl,
    const float* __restrict__ Wr, const float* __restrict__ bl,
    const float* __restrict__ br, float* __restrict__ C,
    int M, int K, int Nh)
{
    const int N = 2 * Nh;
    __shared__ uint32_t As[2][16][136];
    __shared__ uint32_t Bs[2][16][136];
    int tid = threadIdx.x, lane = tid & 31, warp = tid >> 5;
    int wm = warp & 3, wn = warp >> 2;
    int rowBase = blockIdx.y * 128, colBase = blockIdx.x * 128;
    int grp = lane >> 2, tig = lane & 3;

    float acc[2][8][4];
    #pragma unroll
    for (int mt = 0; mt < 2; mt++)
        #pragma unroll
        for (int nt = 0; nt < 8; nt++)
            #pragma unroll
            for (int c = 0; c < 4; c++) acc[mt][nt][c] = 0.f;

    int nIter = K >> 4;
    int arow  = rowBase + (tid >> 1);
    int acol0 = (tid & 1) * 8;
    int brow  = tid >> 4;          // 0..15
    int bcol  = (tid & 15) * 8;    // 0..120
    int gc0   = colBase + bcol;
    int gc1   = gc0 + 4;

    float4 pa, pb, qa, qb;
    const float4 z4 = make_float4(0.f, 0.f, 0.f, 0.f);

    // ---- prologue: tile 0 ----
    pa = pb = z4;
    if (arow < M) {
        pa = *(const float4*)(A + (size_t)arow * K + acol0);
        pb = *(const float4*)(A + (size_t)arow * K + acol0 + 4);
    }
    qa = (gc0 < Nh) ? *(const float4*)(Wl + (size_t)brow * Nh + gc0)
       : (gc0 < N)  ? *(const float4*)(Wr + (size_t)brow * Nh + (gc0 - Nh)) : z4;
    qb = (gc1 < Nh) ? *(const float4*)(Wl + (size_t)brow * Nh + gc1)
       : (gc1 < N)  ? *(const float4*)(Wr + (size_t)brow * Nh + (gc1 - Nh)) : z4;
    {
        int r = tid >> 1;
        As[0][acol0 + 0][r] = f2tf(pa.x); As[0][acol0 + 1][r] = f2tf(pa.y);
        As[0][acol0 + 2][r] = f2tf(pa.z); As[0][acol0 + 3][r] = f2tf(pa.w);
        As[0][acol0 + 4][r] = f2tf(pb.x); As[0][acol0 + 5][r] = f2tf(pb.y);
        As[0][acol0 + 6][r] = f2tf(pb.z); As[0][acol0 + 7][r] = f2tf(pb.w);
        Bs[0][brow][bcol + 0] = f2tf(qa.x); Bs[0][brow][bcol + 1] = f2tf(qa.y);
        Bs[0][brow][bcol + 2] = f2tf(qa.z); Bs[0][brow][bcol + 3] = f2tf(qa.w);
        Bs[0][brow][bcol + 4] = f2tf(qb.x); Bs[0][brow][bcol + 5] = f2tf(qb.y);
        Bs[0][brow][bcol + 6] = f2tf(qb.z); Bs[0][brow][bcol + 7] = f2tf(qb.w);
    }
    __syncthreads();

    int buf = 0;
    for (int it = 0; it < nIter; it++) {
        bool more = (it + 1 < nIter);
        if (more) {
            int k0 = (it + 1) << 4;
            pa = pb = z4;
            if (arow < M) {
                pa = *(const float4*)(A + (size_t)arow * K + k0 + acol0);
                pb = *(const float4*)(A + (size_t)arow * K + k0 + acol0 + 4);
            }
            qa = (gc0 < Nh) ? *(const float4*)(Wl + (size_t)(k0 + brow) * Nh + gc0)
               : (gc0 < N)  ? *(const float4*)(Wr + (size_t)(k0 + brow) * Nh + (gc0 - Nh)) : z4;
            qb = (gc1 < Nh) ? *(const float4*)(Wl + (size_t)(k0 + brow) * Nh + gc1)
               : (gc1 < N)  ? *(const float4*)(Wr + (size_t)(k0 + brow) * Nh + (gc1 - Nh)) : z4;
        }

        #pragma unroll
        for (int ks = 0; ks < 16; ks += 8) {
            uint32_t af[2][4], bf[8][2];
            #pragma unroll
            for (int mt = 0; mt < 2; mt++) {
                int m = wm * 32 + mt * 16;
                af[mt][0] = As[buf][ks + tig][m + grp];
                af[mt][1] = As[buf][ks + tig][m + grp + 8];
                af[mt][2] = As[buf][ks + tig + 4][m + grp];
                af[mt][3] = As[buf][ks + tig + 4][m + grp + 8];
            }
            #pragma unroll
            for (int nt = 0; nt < 8; nt++) {
                int nb = wn * 64 + nt * 8;
                bf[nt][0] = Bs[buf][ks + tig][nb + grp];
                bf[nt][1] = Bs[buf][ks + tig + 4][nb + grp];
            }
            #pragma unroll
            for (int mt = 0; mt < 2; mt++)
                #pragma unroll
                for (int nt = 0; nt < 8; nt++) {
                    asm volatile(
                        "mma.sync.aligned.m16n8k8.row.col.f32.tf32.tf32.f32 "
                        "{%0,%1,%2,%3}, {%4,%5,%6,%7}, {%8,%9}, {%0,%1,%2,%3};"
                        : "+f"(acc[mt][nt][0]), "+f"(acc[mt][nt][1]),
                          "+f"(acc[mt][nt][2]), "+f"(acc[mt][nt][3])
                        : "r"(af[mt][0]), "r"(af[mt][1]), "r"(af[mt][2]), "r"(af[mt][3]),
                          "r"(bf[nt][0]), "r"(bf[nt][1]));
                }
        }

        if (more) {
            int b = buf ^ 1;
            int r = tid >> 1;
            As[b][acol0 + 0][r] = f2tf(pa.x); As[b][acol0 + 1][r] = f2tf(pa.y);
            As[b][acol0 + 2][r] = f2tf(pa.z); As[b][acol0 + 3][r] = f2tf(pa.w);
            As[b][acol0 + 4][r] = f2tf(pb.x); As[b][acol0 + 5][r] = f2tf(pb.y);
            As[b][acol0 + 6][r] = f2tf(pb.z); As[b][acol0 + 7][r] = f2tf(pb.w);
            Bs[b][brow][bcol + 0] = f2tf(qa.x); Bs[b][brow][bcol + 1] = f2tf(qa.y);
            Bs[b][brow][bcol + 2] = f2tf(qa.z); Bs[b][brow][bcol + 3] = f2tf(qa.w);
            Bs[b][brow][bcol + 4] = f2tf(qb.x); Bs[b][brow][bcol + 5] = f2tf(qb.y);
            Bs[b][brow][bcol + 6] = f2tf(qb.z); Bs[b][brow][bcol + 7] = f2tf(qb.w);
            __syncthreads();
        }
        buf ^= 1;
    }

    // epilogue: fused bias from bl/br
    #pragma unroll
    for (int mt = 0; mt < 2; mt++) {
        #pragma unroll
        for (int nt = 0; nt < 8; nt++) {
            int row0 = rowBase + wm * 32 + mt * 16 + grp;
            int col0 = colBase + wn * 64 + nt * 8 + tig * 2;
            if (col0 < N) {
                float b0 = (col0     < Nh) ? bl[col0]     : br[col0 - Nh];
                float b1 = (col0 + 1 < Nh) ? bl[col0 + 1] : br[col0 + 1 - Nh];
                if (row0 < M) {
                    float2 o = make_float2(acc[mt][nt][0] + b0, acc[mt][nt][1] + b1);
                    *(float2*)(C + (size_t)row0 * N + col0) = o;
                }
                if (row0 + 8 < M) {
                    float2 o = make_float2(acc[mt][nt][2] + b0, acc[mt][nt][3] + b1);
                    *(float2*)(C + (size_t)(row0 + 8) * N + col0) = o;
                }
            }
        }
    }
}

// ---------------- layer 1 agg: warp/node, half-warp/edge, depth-3 pipeline ----------------
__global__ __launch_bounds__(256) void agg1_kernel(
    const float* __restrict__ xc, const int* __restrict__ rowptr,
    const int* __restrict__ csrsrc, const float* __restrict__ att,
    const float* __restrict__ bias, float* __restrict__ hout)
{
    int node = (blockIdx.x * blockDim.x + threadIdx.x) >> 5;
    int lane = threadIdx.x & 31;
    if (node >= NN) return;
    int sub = lane >> 4, l = lane & 15;

    const float* vp = xc + (size_t)node * 256 + 128 + l * 8;
    float4 vr0 = *(const float4*)(vp);
    float4 vr1 = *(const float4*)(vp + 4);
    float4 va0 = *(const float4*)(att + l * 8);
    float4 va1 = *(const float4*)(att + l * 8 + 4);

    int beg = rowptr[node], end = rowptr[node + 1];
    int iters = (end - beg + 1) >> 1;
    int sSafe = csrsrc[beg];

    float4 acc0 = make_float4(0.f, 0.f, 0.f, 0.f);
    float4 acc1 = make_float4(0.f, 0.f, 0.f, 0.f);
    float ssum = 0.f;

    int idx = beg + sub;
    bool v0 = idx < end;
    int s0 = v0 ? csrsrc[idx] : sSafe;
    const float* p0 = xc + (size_t)s0 * 256 + l * 8;
    float4 c0 = *(const float4*)p0;
    float4 c1 = *(const float4*)(p0 + 4);

    bool v1 = idx + 2 < end;
    int s1 = v1 ? csrsrc[idx + 2] : sSafe;
    const float* p1 = xc + (size_t)s1 * 256 + l * 8;
    float4 d0 = *(const float4*)p1;
    float4 d1 = *(const float4*)(p1 + 4);

    for (int it = 0; it < iters; it++) {
        bool v2 = idx + 4 < end;
        int s2v = v2 ? csrsrc[idx + 4] : sSafe;
        const float* p2 = xc + (size_t)s2v * 256 + l * 8;
        float4 e0 = *(const float4*)p2;
        float4 e1 = *(const float4*)(p2 + 4);

        float g, sum = 0.f;
        g = c0.x + vr0.x; g = g > 0.f ? g : SLOPE * g; sum += g * va0.x;
        g = c0.y + vr0.y; g = g > 0.f ? g : SLOPE * g; sum += g * va0.y;
        g = c0.z + vr0.z; g = g > 0.f ? g : SLOPE * g; sum += g * va0.z;
        g = c0.w + vr0.w; g = g > 0.f ? g : SLOPE * g; sum += g * va0.w;
        g = c1.x + vr1.x; g = g > 0.f ? g : SLOPE * g; sum += g * va1.x;
        g = c1.y + vr1.y; g = g > 0.f ? g : SLOPE * g; sum += g * va1.y;
        g = c1.z + vr1.z; g = g > 0.f ? g : SLOPE * g; sum += g * va1.z;
        g = c1.w + vr1.w; g = g > 0.f ? g : SLOPE * g; sum += g * va1.w;
        sum += __shfl_xor_sync(FULLMASK, sum, 1);
        sum += __shfl_xor_sync(FULLMASK, sum, 2);
        float a = v0 ? __expf(sum) : 0.f;
        acc0.x += a * c0.x; acc0.y += a * c0.y; acc0.z += a * c0.z; acc0.w += a * c0.w;
        acc1.x += a * c1.x; acc1.y += a * c1.y; acc1.z += a * c1.z; acc1.w += a * c1.w;
        ssum += a;

        c0 = d0; c1 = d1; v0 = v1;
        d0 = e0; d1 = e1; v1 = v2;
        idx += 2;
    }

    acc0.x += __shfl_xor_sync(FULLMASK, acc0.x, 16);
    acc0.y += __shfl_xor_sync(FULLMASK, acc0.y, 16);
    acc0.z += __shfl_xor_sync(FULLMASK, acc0.z, 16);
    acc0.w += __shfl_xor_sync(FULLMASK, acc0.w, 16);
    acc1.x += __shfl_xor_sync(FULLMASK, acc1.x, 16);
    acc1.y += __shfl_xor_sync(FULLMASK, acc1.y, 16);
    acc1.z += __shfl_xor_sync(FULLMASK, acc1.z, 16);
    acc1.w += __shfl_xor_sync(FULLMASK, acc1.w, 16);
    ssum   += __shfl_xor_sync(FULLMASK, ssum,   16);

    if (sub == 0) {
        float inv = 1.f / (ssum + 1e-16f);
        float4 b0 = *(const float4*)(bias + l * 8);
        float4 b1 = *(const float4*)(bias + l * 8 + 4);
        float4 o0, o1;
        o0.x = acc0.x * inv + b0.x; o0.y = acc0.y * inv + b0.y;
        o0.z = acc0.z * inv + b0.z; o0.w = acc0.w * inv + b0.w;
        o1.x = acc1.x * inv + b1.x; o1.y = acc1.y * inv + b1.y;
        o1.z = acc1.z * inv + b1.z; o1.w = acc1.w * inv + b1.w;
        o0.x = o0.x > 0.f ? o0.x : (__expf(o0.x) - 1.f);
        o0.y = o0.y > 0.f ? o0.y : (__expf(o0.y) - 1.f);
        o0.z = o0.z > 0.f ? o0.z : (__expf(o0.z) - 1.f);
        o0.w = o0.w > 0.f ? o0.w : (__expf(o0.w) - 1.f);
        o1.x = o1.x > 0.f ? o1.x : (__expf(o1.x) - 1.f);
        o1.y = o1.y > 0.f ? o1.y : (__expf(o1.y) - 1.f);
        o1.z = o1.z > 0.f ? o1.z : (__expf(o1.z) - 1.f);
        o1.w = o1.w > 0.f ? o1.w : (__expf(o1.w) - 1.f);
        *(float4*)(hout + (size_t)node * F1 + l * 8)     = o0;
        *(float4*)(hout + (size_t)node * F1 + l * 8 + 4) = o1;
    }
}

// ---------------- layer 2 agg: warp/node, half-warp/edge, depth-3 pipeline ----------------
__global__ __launch_bounds__(256) void agg2_kernel(
    const float* __restrict__ xc, const int* __restrict__ rowptr,
    const int* __restrict__ csrsrc, const float* __restrict__ att,
    const float* __restrict__ bias, float* __restrict__ out)
{
    int node = (blockIdx.x * blockDim.x + threadIdx.x) >> 5;
    int lane = threadIdx.x & 31;
    if (node >= NN) return;
    int sub = lane >> 4, l = lane & 15;
    int base = l * 10;   // head = l>>2

    float2 vr[5], va[5];
    const float* vp = xc + (size_t)node * 320 + 160 + base;
    #pragma unroll
    for (int j = 0; j < 5; j++) {
        vr[j] = *(const float2*)(vp + 2 * j);
        va[j] = *(const float2*)(att + base + 2 * j);
    }

    int beg = rowptr[node], end = rowptr[node + 1];
    int iters = (end - beg + 1) >> 1;
    int sSafe = csrsrc[beg];

    float2 acc[5];
    #pragma unroll
    for (int j = 0; j < 5; j++) acc[j] = make_float2(0.f, 0.f);
    float ssum = 0.f;

    int idx = beg + sub;
    bool v0 = idx < end;
    int s0 = v0 ? csrsrc[idx] : sSafe;
    float2 cur[5], nx1[5];
    {
        const float* sp = xc + (size_t)s0 * 320 + base;
        #pragma unroll
        for (int j = 0; j < 5; j++) cur[j] = *(const float2*)(sp + 2 * j);
    }
    bool v1 = idx + 2 < end;
    int s1 = v1 ? csrsrc[idx + 2] : sSafe;
    {
        const float* sp = xc + (size_t)s1 * 320 + base;
        #pragma unroll
        for (int j = 0; j < 5; j++) nx1[j] = *(const float2*)(sp + 2 * j);
    }

    for (int it = 0; it < iters; it++) {
        bool v2 = idx + 4 < end;
        int s2v = v2 ? csrsrc[idx + 4] : sSafe;
        float2 nx2[5];
        {
            const float* sp = xc + (size_t)s2v * 320 + base;
            #pragma unroll
            for (int j = 0; j < 5; j++) nx2[j] = *(const float2*)(sp + 2 * j);
        }
        float sum = 0.f;
        #pragma unroll
        for (int j = 0; j < 5; j++) {
            float g = cur[j].x + vr[j].x; g = g > 0.f ? g : SLOPE * g; sum += g * va[j].x;
            g       = cur[j].y + vr[j].y; g = g > 0.f ? g : SLOPE * g; sum += g * va[j].y;
        }
        sum += __shfl_xor_sync(FULLMASK, sum, 1);
        sum += __shfl_xor_sync(FULLMASK, sum, 2);
        float a = v0 ? __expf(sum) : 0.f;
        #pragma unroll
        for (int j = 0; j < 5; j++) { acc[j].x += a * cur[j].x; acc[j].y += a * cur[j].y; }
        ssum += a;
        #pragma unroll
        for (int j = 0; j < 5; j++) { cur[j] = nx1[j]; nx1[j] = nx2[j]; }
        v0 = v1; v1 = v2;
        idx += 2;
    }

    #pragma unroll
    for (int j = 0; j < 5; j++) {
        acc[j].x += __shfl_xor_sync(FULLMASK, acc[j].x, 16);
        acc[j].y += __shfl_xor_sync(FULLMASK, acc[j].y, 16);
    }
    ssum += __shfl_xor_sync(FULLMASK, ssum, 16);

    float inv = 1.f / (ssum + 1e-16f);
    #pragma unroll
    for (int j = 0; j < 5; j++) {
        float vx = acc[j].x * inv, vy = acc[j].y * inv;
        vx += __shfl_xor_sync(FULLMASK, vx, 4);
        vx += __shfl_xor_sync(FULLMASK, vx, 8);
        vy += __shfl_xor_sync(FULLMASK, vy, 4);
        vy += __shfl_xor_sync(FULLMASK, vy, 8);
        acc[j].x = vx; acc[j].y = vy;
    }

    if (sub == 0 && l < 4) {
        #pragma unroll
        for (int j = 0; j < 5; j++) {
            float2 o;
            o.x = 0.25f * acc[j].x + bias[base + 2 * j];
            o.y = 0.25f * acc[j].y + bias[base + 2 * j + 1];
            *(float2*)(out + (size_t)node * OUT_DIM + base + 2 * j) = o;
        }
    }
}

// ---------------- host ----------------
struct Ptrs {
    float *xc1, *xc2, *h;
    int *deg, *rowptr, *csrsrc;
};
static Ptrs P;
static cudaStream_t g_s2;
static cudaEvent_t g_ev1, g_ev2;
static bool g_init = false;

extern "C" void kernel_launch(void* const* d_in, const int* in_sizes, int n_in,
                              void* d_out, int out_size)
{
    if (!g_init) {
        cudaGetSymbolAddress((void**)&P.xc1,    g_xc1);
        cudaGetSymbolAddress((void**)&P.xc2,    g_xc2);
        cudaGetSymbolAddress((void**)&P.h,      g_h);
        cudaGetSymbolAddress((void**)&P.deg,    g_deg);
        cudaGetSymbolAddress((void**)&P.rowptr, g_rowptr);
        cudaGetSymbolAddress((void**)&P.csrsrc, g_csrsrc);
        cudaStreamCreateWithFlags(&g_s2, cudaStreamNonBlocking);
        cudaEventCreateWithFlags(&g_ev1, cudaEventDisableTiming);
        cudaEventCreateWithFlags(&g_ev2, cudaEventDisableTiming);
        g_init = true;
    }

    const float* x     = (const float*)d_in[0];
    const int*   ei    = (const int*)  d_in[1];
    const float* Wl1   = (const float*)d_in[2];
    const float* bl1   = (const float*)d_in[3];
    const float* Wr1   = (const float*)d_in[4];
    const float* br1   = (const float*)d_in[5];
    const float* att1  = (const float*)d_in[6];
    const float* bias1 = (const float*)d_in[7];
    const float* Wl2   = (const float*)d_in[8];
    const float* bl2   = (const float*)d_in[9];
    const float* Wr2   = (const float*)d_in[10];
    const float* br2   = (const float*)d_in[11];
    const float* att2  = (const float*)d_in[12];
    const float* bias2 = (const float*)d_in[13];
    float* out = (float*)d_out;

    const int* esrc = ei;
    const int* edst = ei + EE;

    // fork: CSR build on side stream, GEMM1 on main stream (independent)
    cudaEventRecord(g_ev1, 0);
    cudaStreamWaitEvent(g_s2, g_ev1, 0);
    cudaMemsetAsync(P.deg, 0, NN * sizeof(int), g_s2);
    count_kernel<<<(ET + 255) / 256, 256, 0, g_s2>>>(edst);
    scan_kernel<<<1, 1024, 0, g_s2>>>();
    scatter_kernel<<<(ET + 255) / 256, 256, 0, g_s2>>>(esrc, edst);
    cudaEventRecord(g_ev2, g_s2);

    // ----- layer 1 GEMM (main stream, concurrent with CSR build) -----
    {
        dim3 grid(2, (NN + 127) / 128);
        gemm_tf32_fused<<<grid, 256>>>(x, Wl1, Wr1, bl1, br1, P.xc1, NN, IN_DIM, F1);
    }
    // join: agg1 needs both GEMM1 and CSR
    cudaStreamWaitEvent(0, g_ev2, 0);
    agg1_kernel<<<(NN * 32 + 255) / 256, 256>>>(P.xc1, P.rowptr, P.csrsrc, att1, bias1, P.h);

    // ----- layer 2 -----
    {
        dim3 grid(3, (NN + 127) / 128);
        gemm_tf32_fused<<<grid, 256>>>(P.h, Wl2, Wr2, bl2, br2, P.xc2, NN, F1, F2);
    }
    agg2_kernel<<<(NN * 32 + 255) / 256, 256>>>(P.xc2, P.rowptr, P.csrsrc, att2, bias2, out);
}

// round 6
// speedup vs baseline: 1.1657x; 1.1657x over previous
#include <cuda_runtime.h>
#include <cstdint>

#define NN      50000
#define EE      800000
#define ET      (EE + NN)
#define IN_DIM  256
#define HID     32
#define HEADS   4
#define OUT_DIM 40
#define F1      128
#define F2      160
#define SLOPE   0.2f
#define FULLMASK 0xffffffffu

// ---------------- scratch ----------------
__device__ float g_xc1[(size_t)NN * 256];   // [xl1 | xr1]
__device__ float g_xc2[(size_t)NN * 320];   // [xl2 | xr2]
__device__ float g_h  [(size_t)NN * F1];
__device__ int   g_deg[NN];
__device__ int   g_rowptr[NN + 1];
__device__ int   g_cursor[NN];
__device__ int   g_csrsrc[ET];

// ---------------- CSR build ----------------
__global__ void count_kernel(const int* __restrict__ edst)
{
    int idx = blockIdx.x * blockDim.x + threadIdx.x;
    if (idx >= ET) return;
    int d = (idx < EE) ? edst[idx] : idx - EE;
    atomicAdd(&g_deg[d], 1);
}

__global__ void scan_kernel()
{
    __shared__ int ssum[1024];
    int t = threadIdx.x;
    const int CH = (NN + 1023) / 1024;
    int lo = t * CH;
    int hi = min(lo + CH, NN);
    int s = 0;
    for (int i = lo; i < hi; i++) s += g_deg[i];
    ssum[t] = s;
    __syncthreads();
    for (int off = 1; off < 1024; off <<= 1) {
        int v = (t >= off) ? ssum[t - off] : 0;
        __syncthreads();
        ssum[t] += v;
        __syncthreads();
    }
    int base = (t == 0) ? 0 : ssum[t - 1];
    for (int i = lo; i < hi; i++) {
        g_rowptr[i] = base;
        g_cursor[i] = base;
        base += g_deg[i];
    }
    if (t == 0) g_rowptr[NN] = ET;
}

__global__ void scatter_kernel(const int* __restrict__ esrc, const int* __restrict__ edst)
{
    int idx = blockIdx.x * blockDim.x + threadIdx.x;
    if (idx >= ET) return;
    int s, d;
    if (idx < EE) { s = esrc[idx]; d = edst[idx]; }
    else          { s = d = idx - EE; }
    int pos = atomicAdd(&g_cursor[d], 1);
    g_csrsrc[pos] = s;
}

// ---------------- TF32 GEMM, cp.async double-buffered, fused concat+bias ----------------
__device__ __forceinline__ uint32_t f2tf(float f) {
    uint32_t r;
    asm("cvt.rna.tf32.f32 %0, %1;" : "=r"(r) : "f"(f));
    return r;
}
__device__ __forceinline__ void cpa16(uint32_t d, const void* s, int sz) {
    asm volatile("cp.async.cg.shared.global [%0], [%1], 16, %2;"
                 :: "r"(d), "l"(s), "r"(sz));
}

// C[M, 2*Nh] = A[M,K] @ [Wl | Wr] + [bl | br]
__global__ __launch_bounds__(256, 2) void gemm_tf32_fused(
    const float* __restrict__ A, const float* __restrict__ Wl,
    const float* __restrict__ Wr, const float* __restrict__ bl,
    const float* __restrict__ br, float* __restrict__ C,
    int M, int K, int Nh)
{
    const int N = 2 * Nh;
    __shared__ uint32_t As[2][16][136];
    __shared__ float    Bs[2][16][136];
    int tid = threadIdx.x, lane = tid & 31, warp = tid >> 5;
    int wm = warp & 3, wn = warp >> 2;
    int rowBase = blockIdx.y * 128, colBase = blockIdx.x * 128;
    int grp = lane >> 2, tig = lane & 3;

    float acc[2][8][4];
    #pragma unroll
    for (int mt = 0; mt < 2; mt++)
        #pragma unroll
        for (int nt = 0; nt < 8; nt++)
            #pragma unroll
            for (int c = 0; c < 4; c++) acc[mt][nt][c] = 0.f;

    int nIter = K >> 4;

    float4 pa, pb;
    // prologue: tile 0
    {
        int gr = rowBase + (tid >> 1);
        int kc = (tid & 1) * 8;
        pa = make_float4(0.f, 0.f, 0.f, 0.f); pb = pa;
        if (gr < M) {
            pa = *(const float4*)(A + (size_t)gr * K + kc);
            pb = *(const float4*)(A + (size_t)gr * K + kc + 4);
        }
    }
    {
        int rB = tid >> 4;
        int cB = (tid & 15) * 8;
        #pragma unroll
        for (int i = 0; i < 2; i++) {
            int gc = colBase + cB + i * 4;
            const float* src = Wl; int sz = 0;
            if (gc < Nh)      { src = Wl + (size_t)rB * Nh + gc;        sz = 16; }
            else if (gc < N)  { src = Wr + (size_t)rB * Nh + (gc - Nh); sz = 16; }
            cpa16((uint32_t)__cvta_generic_to_shared(&Bs[0][rB][cB + i * 4]), src, sz);
        }
    }
    {
        int r = tid >> 1, c4 = (tid & 1) * 8;
        As[0][c4 + 0][r] = f2tf(pa.x); As[0][c4 + 1][r] = f2tf(pa.y);
        As[0][c4 + 2][r] = f2tf(pa.z); As[0][c4 + 3][r] = f2tf(pa.w);
        As[0][c4 + 4][r] = f2tf(pb.x); As[0][c4 + 5][r] = f2tf(pb.y);
        As[0][c4 + 6][r] = f2tf(pb.z); As[0][c4 + 7][r] = f2tf(pb.w);
    }
    asm volatile("cp.async.commit_group;");

    int buf = 0;
    for (int it = 0; it < nIter; it++) {
        asm volatile("cp.async.wait_group 0;");
        __syncthreads();
        bool more = (it + 1 < nIter);
        if (more) {
            int k0 = (it + 1) << 4;
            int gr = rowBase + (tid >> 1);
            int kc = k0 + (tid & 1) * 8;
            pa = make_float4(0.f, 0.f, 0.f, 0.f); pb = pa;
            if (gr < M) {
                pa = *(const float4*)(A + (size_t)gr * K + kc);
                pb = *(const float4*)(A + (size_t)gr * K + kc + 4);
            }
            int rB = tid >> 4;
            int cB = (tid & 15) * 8;
            #pragma unroll
            for (int i = 0; i < 2; i++) {
                int gc = colBase + cB + i * 4;
                const float* src = Wl; int sz = 0;
                if (gc < Nh)      { src = Wl + (size_t)(k0 + rB) * Nh + gc;        sz = 16; }
                else if (gc < N)  { src = Wr + (size_t)(k0 + rB) * Nh + (gc - Nh); sz = 16; }
                cpa16((uint32_t)__cvta_generic_to_shared(&Bs[buf ^ 1][rB][cB + i * 4]), src, sz);
            }
            asm volatile("cp.async.commit_group;");
        }

        #pragma unroll
        for (int ks = 0; ks < 16; ks += 8) {
            uint32_t af[2][4], bf[8][2];
            #pragma unroll
            for (int mt = 0; mt < 2; mt++) {
                int m = wm * 32 + mt * 16;
                af[mt][0] = As[buf][ks + tig][m + grp];
                af[mt][1] = As[buf][ks + tig][m + grp + 8];
                af[mt][2] = As[buf][ks + tig + 4][m + grp];
                af[mt][3] = As[buf][ks + tig + 4][m + grp + 8];
            }
            #pragma unroll
            for (int nt = 0; nt < 8; nt++) {
                int nb = wn * 64 + nt * 8;
                bf[nt][0] = f2tf(Bs[buf][ks + tig][nb + grp]);
                bf[nt][1] = f2tf(Bs[buf][ks + tig + 4][nb + grp]);
            }
            #pragma unroll
            for (int mt = 0; mt < 2; mt++)
                #pragma unroll
                for (int nt = 0; nt < 8; nt++) {
                    asm volatile(
                        "mma.sync.aligned.m16n8k8.row.col.f32.tf32.tf32.f32 "
                        "{%0,%1,%2,%3}, {%4,%5,%6,%7}, {%8,%9}, {%0,%1,%2,%3};"
                        : "+f"(acc[mt][nt][0]), "+f"(acc[mt][nt][1]),
                          "+f"(acc[mt][nt][2]), "+f"(acc[mt][nt][3])
                        : "r"(af[mt][0]), "r"(af[mt][1]), "r"(af[mt][2]), "r"(af[mt][3]),
                          "r"(bf[nt][0]), "r"(bf[nt][1]));
                }
        }

        if (more) {
            int r = tid >> 1, c4 = (tid & 1) * 8;
            int b = buf ^ 1;
            As[b][c4 + 0][r] = f2tf(pa.x); As[b][c4 + 1][r] = f2tf(pa.y);
            As[b][c4 + 2][r] = f2tf(pa.z); As[b][c4 + 3][r] = f2tf(pa.w);
            As[b][c4 + 4][r] = f2tf(pb.x); As[b][c4 + 5][r] = f2tf(pb.y);
            As[b][c4 + 6][r] = f2tf(pb.z); As[b][c4 + 7][r] = f2tf(pb.w);
        }
        buf ^= 1;
    }

    // epilogue: fused bias from bl/br
    #pragma unroll
    for (int mt = 0; mt < 2; mt++) {
        #pragma unroll
        for (int nt = 0; nt < 8; nt++) {
            int row0 = rowBase + wm * 32 + mt * 16 + grp;
            int col0 = colBase + wn * 64 + nt * 8 + tig * 2;
            if (col0 < N) {
                float b0 = (col0     < Nh) ? bl[col0]     : br[col0 - Nh];
                float b1 = (col0 + 1 < Nh) ? bl[col0 + 1] : br[col0 + 1 - Nh];
                if (row0 < M) {
                    float2 o = make_float2(acc[mt][nt][0] + b0, acc[mt][nt][1] + b1);
                    *(float2*)(C + (size_t)row0 * N + col0) = o;
                }
                if (row0 + 8 < M) {
                    float2 o = make_float2(acc[mt][nt][2] + b0, acc[mt][nt][3] + b1);
                    *(float2*)(C + (size_t)(row0 + 8) * N + col0) = o;
                }
            }
        }
    }
}

// ---------------- layer 1 agg: warp/node, half-warp/edge, depth-2 prefetch ----------------
__global__ __launch_bounds__(256) void agg1_kernel(
    const float* __restrict__ xc, const int* __restrict__ rowptr,
    const int* __restrict__ csrsrc, const float* __restrict__ att,
    const float* __restrict__ bias, float* __restrict__ hout)
{
    int node = (blockIdx.x * blockDim.x + threadIdx.x) >> 5;
    int lane = threadIdx.x & 31;
    if (node >= NN) return;
    int sub = lane >> 4, l = lane & 15;

    const float* vp = xc + (size_t)node * 256 + 128 + l * 8;
    float4 vr0 = *(const float4*)(vp);
    float4 vr1 = *(const float4*)(vp + 4);
    float4 va0 = *(const float4*)(att + l * 8);
    float4 va1 = *(const float4*)(att + l * 8 + 4);

    int beg = rowptr[node], end = rowptr[node + 1];
    int deg = end - beg;
    int iters = (deg + 1) >> 1;

    float4 acc0 = make_float4(0.f, 0.f, 0.f, 0.f);
    float4 acc1 = make_float4(0.f, 0.f, 0.f, 0.f);
    float ssum = 0.f;

    int idx = beg + sub;
    bool v = idx < end;
    int s = v ? csrsrc[idx] : csrsrc[beg];
    const float* sp = xc + (size_t)s * 256 + l * 8;
    float4 c0 = *(const float4*)sp;
    float4 c1 = *(const float4*)(sp + 4);

    for (int it = 0; it < iters; it++) {
        int idxn = idx + 2;
        bool vn = idxn < end;
        int sn = vn ? csrsrc[idxn] : csrsrc[beg];
        const float* np = xc + (size_t)sn * 256 + l * 8;
        float4 n0 = *(const float4*)np;
        float4 n1 = *(const float4*)(np + 4);

        float g, sum = 0.f;
        g = c0.x + vr0.x; g = g > 0.f ? g : SLOPE * g; sum += g * va0.x;
        g = c0.y + vr0.y; g = g > 0.f ? g : SLOPE * g; sum += g * va0.y;
        g = c0.z + vr0.z; g = g > 0.f ? g : SLOPE * g; sum += g * va0.z;
        g = c0.w + vr0.w; g = g > 0.f ? g : SLOPE * g; sum += g * va0.w;
        g = c1.x + vr1.x; g = g > 0.f ? g : SLOPE * g; sum += g * va1.x;
        g = c1.y + vr1.y; g = g > 0.f ? g : SLOPE * g; sum += g * va1.y;
        g = c1.z + vr1.z; g = g > 0.f ? g : SLOPE * g; sum += g * va1.z;
        g = c1.w + vr1.w; g = g > 0.f ? g : SLOPE * g; sum += g * va1.w;
        sum += __shfl_xor_sync(FULLMASK, sum, 1);
        sum += __shfl_xor_sync(FULLMASK, sum, 2);
        float a = v ? __expf(sum) : 0.f;
        acc0.x += a * c0.x; acc0.y += a * c0.y; acc0.z += a * c0.z; acc0.w += a * c0.w;
        acc1.x += a * c1.x; acc1.y += a * c1.y; acc1.z += a * c1.z; acc1.w += a * c1.w;
        ssum += a;
        c0 = n0; c1 = n1; v = vn; idx = idxn;
    }

    acc0.x += __shfl_xor_sync(FULLMASK, acc0.x, 16);
    acc0.y += __shfl_xor_sync(FULLMASK, acc0.y, 16);
    acc0.z += __shfl_xor_sync(FULLMASK, acc0.z, 16);
    acc0.w += __shfl_xor_sync(FULLMASK, acc0.w, 16);
    acc1.x += __shfl_xor_sync(FULLMASK, acc1.x, 16);
    acc1.y += __shfl_xor_sync(FULLMASK, acc1.y, 16);
    acc1.z += __shfl_xor_sync(FULLMASK, acc1.z, 16);
    acc1.w += __shfl_xor_sync(FULLMASK, acc1.w, 16);
    ssum   += __shfl_xor_sync(FULLMASK, ssum,   16);

    if (sub == 0) {
        float inv = 1.f / (ssum + 1e-16f);
        float4 b0 = *(const float4*)(bias + l * 8);
        float4 b1 = *(const float4*)(bias + l * 8 + 4);
        float4 o0, o1;
        o0.x = acc0.x * inv + b0.x; o0.y = acc0.y * inv + b0.y;
        o0.z = acc0.z * inv + b0.z; o0.w = acc0.w * inv + b0.w;
        o1.x = acc1.x * inv + b1.x; o1.y = acc1.y * inv + b1.y;
        o1.z = acc1.z * inv + b1.z; o1.w = acc1.w * inv + b1.w;
        o0.x = o0.x > 0.f ? o0.x : (__expf(o0.x) - 1.f);
        o0.y = o0.y > 0.f ? o0.y : (__expf(o0.y) - 1.f);
        o0.z = o0.z > 0.f ? o0.z : (__expf(o0.z) - 1.f);
        o0.w = o0.w > 0.f ? o0.w : (__expf(o0.w) - 1.f);
        o1.x = o1.x > 0.f ? o1.x : (__expf(o1.x) - 1.f);
        o1.y = o1.y > 0.f ? o1.y : (__expf(o1.y) - 1.f);
        o1.z = o1.z > 0.f ? o1.z : (__expf(o1.z) - 1.f);
        o1.w = o1.w > 0.f ? o1.w : (__expf(o1.w) - 1.f);
        *(float4*)(hout + (size_t)node * F1 + l * 8)     = o0;
        *(float4*)(hout + (size_t)node * F1 + l * 8 + 4) = o1;
    }
}

// ---------------- layer 2 agg: warp/node, half-warp/edge, depth-2 prefetch ----------------
__global__ __launch_bounds__(256) void agg2_kernel(
    const float* __restrict__ xc, const int* __restrict__ rowptr,
    const int* __restrict__ csrsrc, const float* __restrict__ att,
    const float* __restrict__ bias, float* __restrict__ out)
{
    int node = (blockIdx.x * blockDim.x + threadIdx.x) >> 5;
    int lane = threadIdx.x & 31;
    if (node >= NN) return;
    int sub = lane >> 4, l = lane & 15;
    int base = l * 10;   // head = l>>2

    float2 vr[5], va[5];
    const float* vp = xc + (size_t)node * 320 + 160 + base;
    #pragma unroll
    for (int j = 0; j < 5; j++) {
        vr[j] = *(const float2*)(vp + 2 * j);
        va[j] = *(const float2*)(att + base + 2 * j);
    }

    int beg = rowptr[node], end = rowptr[node + 1];
    int deg = end - beg;
    int iters = (deg + 1) >> 1;

    float2 acc[5];
    #pragma unroll
    for (int j = 0; j < 5; j++) acc[j] = make_float2(0.f, 0.f);
    float ssum = 0.f;

    int idx = beg + sub;
    bool v = idx < end;
    int s = v ? csrsrc[idx] : csrsrc[beg];
    float2 cur[5];
    {
        const float* sp = xc + (size_t)s * 320 + base;
        #pragma unroll
        for (int j = 0; j < 5; j++) cur[j] = *(const float2*)(sp + 2 * j);
    }

    for (int it = 0; it < iters; it++) {
        int idxn = idx + 2;
        bool vn = idxn < end;
        int sn = vn ? csrsrc[idxn] : csrsrc[beg];
        float2 nxt[5];
        {
            const float* sp = xc + (size_t)sn * 320 + base;
            #pragma unroll
            for (int j = 0; j < 5; j++) nxt[j] = *(const float2*)(sp + 2 * j);
        }
        float sum = 0.f;
        #pragma unroll
        for (int j = 0; j < 5; j++) {
            float g = cur[j].x + vr[j].x; g = g > 0.f ? g : SLOPE * g; sum += g * va[j].x;
            g       = cur[j].y + vr[j].y; g = g > 0.f ? g : SLOPE * g; sum += g * va[j].y;
        }
        sum += __shfl_xor_sync(FULLMASK, sum, 1);
        sum += __shfl_xor_sync(FULLMASK, sum, 2);
        float a = v ? __expf(sum) : 0.f;
        #pragma unroll
        for (int j = 0; j < 5; j++) { acc[j].x += a * cur[j].x; acc[j].y += a * cur[j].y; }
        ssum += a;
        #pragma unroll
        for (int j = 0; j < 5; j++) cur[j] = nxt[j];
        v = vn; idx = idxn;
    }

    #pragma unroll
    for (int j = 0; j < 5; j++) {
        acc[j].x += __shfl_xor_sync(FULLMASK, acc[j].x, 16);
        acc[j].y += __shfl_xor_sync(FULLMASK, acc[j].y, 16);
    }
    ssum += __shfl_xor_sync(FULLMASK, ssum, 16);

    float inv = 1.f / (ssum + 1e-16f);
    #pragma unroll
    for (int j = 0; j < 5; j++) {
        float vx = acc[j].x * inv, vy = acc[j].y * inv;
        vx += __shfl_xor_sync(FULLMASK, vx, 4);
        vx += __shfl_xor_sync(FULLMASK, vx, 8);
        vy += __shfl_xor_sync(FULLMASK, vy, 4);
        vy += __shfl_xor_sync(FULLMASK, vy, 8);
        acc[j].x = vx; acc[j].y = vy;
    }

    if (sub == 0 && l < 4) {
        #pragma unroll
        for (int j = 0; j < 5; j++) {
            float2 o;
            o.x = 0.25f * acc[j].x + bias[base + 2 * j];
            o.y = 0.25f * acc[j].y + bias[base + 2 * j + 1];
            *(float2*)(out + (size_t)node * OUT_DIM + base + 2 * j) = o;
        }
    }
}

// ---------------- host ----------------
struct Ptrs {
    float *xc1, *xc2, *h;
    int *deg, *rowptr, *csrsrc;
};
static Ptrs P;
static cudaStream_t g_s2;
static cudaEvent_t g_ev1, g_ev2;
static bool g_init = false;

extern "C" void kernel_launch(void* const* d_in, const int* in_sizes, int n_in,
                              void* d_out, int out_size)
{
    if (!g_init) {
        cudaGetSymbolAddress((void**)&P.xc1,    g_xc1);
        cudaGetSymbolAddress((void**)&P.xc2,    g_xc2);
        cudaGetSymbolAddress((void**)&P.h,      g_h);
        cudaGetSymbolAddress((void**)&P.deg,    g_deg);
        cudaGetSymbolAddress((void**)&P.rowptr, g_rowptr);
        cudaGetSymbolAddress((void**)&P.csrsrc, g_csrsrc);
        cudaStreamCreateWithFlags(&g_s2, cudaStreamNonBlocking);
        cudaEventCreateWithFlags(&g_ev1, cudaEventDisableTiming);
        cudaEventCreateWithFlags(&g_ev2, cudaEventDisableTiming);
        g_init = true;
    }

    const float* x     = (const float*)d_in[0];
    const int*   ei    = (const int*)  d_in[1];
    const float* Wl1   = (const float*)d_in[2];
    const float* bl1   = (const float*)d_in[3];
    const float* Wr1   = (const float*)d_in[4];
    const float* br1   = (const float*)d_in[5];
    const float* att1  = (const float*)d_in[6];
    const float* bias1 = (const float*)d_in[7];
    const float* Wl2   = (const float*)d_in[8];
    const float* bl2   = (const float*)d_in[9];
    const float* Wr2   = (const float*)d_in[10];
    const float* br2   = (const float*)d_in[11];
    const float* att2  = (const float*)d_in[12];
    const float* bias2 = (const float*)d_in[13];
    float* out = (float*)d_out;

    const int* esrc = ei;
    const int* edst = ei + EE;

    // fork: CSR build on side stream, concurrent with GEMM1
    cudaEventRecord(g_ev1, 0);
    cudaStreamWaitEvent(g_s2, g_ev1, 0);
    cudaMemsetAsync(P.deg, 0, NN * sizeof(int), g_s2);
    count_kernel<<<(ET + 255) / 256, 256, 0, g_s2>>>(edst);
    scan_kernel<<<1, 1024, 0, g_s2>>>();
    scatter_kernel<<<(ET + 255) / 256, 256, 0, g_s2>>>(esrc, edst);
    cudaEventRecord(g_ev2, g_s2);

    // ----- layer 1 GEMM (main stream) -----
    {
        dim3 grid(2, (NN + 127) / 128);
        gemm_tf32_fused<<<grid, 256>>>(x, Wl1, Wr1, bl1, br1, P.xc1, NN, IN_DIM, F1);
    }
    // join: agg1 needs both GEMM1 and CSR
    cudaStreamWaitEvent(0, g_ev2, 0);
    agg1_kernel<<<(NN * 32 + 255) / 256, 256>>>(P.xc1, P.rowptr, P.csrsrc, att1, bias1, P.h);

    // ----- layer 2 -----
    {
        dim3 grid(3, (NN + 127) / 128);
        gemm_tf32_fused<<<grid, 256>>>(P.h, Wl2, Wr2, bl2, br2, P.xc2, NN, F1, F2);
    }
    agg2_kernel<<<(NN * 32 + 255) / 256, 256>>>(P.xc2, P.rowptr, P.csrsrc, att2, bias2, out);
}